// round 14
// baseline (speedup 1.0000x reference)
#include <cuda_runtime.h>
#include <cuda_bf16.h>
#include <cstdint>

// Problem constants (fixed by the dataset): B=1024, T=512, K=64 tags.
#define KTAG 64
#define MAXB 1024
#define MAXT 512
#define NEGV -10000.0f

// Scratch: g_m[b][t][j] = max_prev(fv_prev + w[j][prev]) BEFORE emission.
__device__ float g_m[(size_t)MAXB * MAXT * KTAG];
__device__ float g_scratch[(size_t)MAXB * MAXT];
__device__ float g_scratch_score[MAXB];
__device__ int   g_order[MAXB];     // batch ids, descending len (LPT)
__device__ int   g_next;            // work-stealing counter

// ---- packed f32x2 add; movs are register-pairing only (elided by ptxas) ----
__device__ __forceinline__ float2 fadd2(float2 a, float2 b) {
    float2 r;
    asm("{\n\t"
        ".reg .b64 ra, rb, rc;\n\t"
        "mov.b64 ra, {%2, %3};\n\t"
        "mov.b64 rb, {%4, %5};\n\t"
        "add.rn.f32x2 rc, ra, rb;\n\t"
        "mov.b64 {%0, %1}, rc;\n\t"
        "}"
        : "=f"(r.x), "=f"(r.y)
        : "f"(a.x), "f"(a.y), "f"(b.x), "f"(b.y));
    return r;
}

// ---- cp.async helpers ----
__device__ __forceinline__ void cp_async16(void* smem_dst, const void* gmem_src) {
    unsigned int d = (unsigned int)__cvta_generic_to_shared(smem_dst);
    asm volatile("cp.async.cg.shared.global [%0], [%1], 16;" :: "r"(d), "l"(gmem_src));
}
#define CP_COMMIT()  asm volatile("cp.async.commit_group;")
#define CP_WAIT(n)   asm volatile("cp.async.wait_group %0;" :: "n"(n))

#define CH 8             // backward: timesteps per staged chunk
#define GRID_PERSIST 592 // 4 blocks/SM on 148 SMs

// ============================================================================
// Prologue: counting-sort batches by DESCENDING len into g_order (LPT order).
// ============================================================================
__global__ void crf_order(const int* __restrict__ lens, int B, int T)
{
    __shared__ int hist[MAXT + 1];
    __shared__ int off[MAXT + 1];
    const int tid = threadIdx.x;
    const int nt = blockDim.x;

    for (int l = tid; l <= T; l += nt) hist[l] = 0;
    __syncthreads();
    for (int b = tid; b < B; b += nt) atomicAdd(&hist[lens[b]], 1);
    __syncthreads();
    if (tid == 0) {
        int acc = 0;
        for (int l = T; l >= 0; --l) { off[l] = acc; acc += hist[l]; }
        g_next = 0;
    }
    __syncthreads();
    for (int b = tid; b < B; b += nt) {
        int pos = atomicAdd(&off[lens[b]], 1);
        g_order[pos] = b;
    }
}

// ============================================================================
// Persistent fused Viterbi: 128 threads = TWO batch-lanes sharing cheap
// block barriers. Pair 0 = warps 0/1 (SMSP 0/1); pair 1 = warps 2/3 (SMSP
// 2/3) — all four schedulers fed. Each block grabs TWO ADJACENT entries of
// the descending-len order, so len0 ~= len1 and the coupled loop to
// max(len0,len1) wastes ~nothing.
//   Forward: thread j of a pair owns next-tag j; FADD2 adds, FMNMX maxes,
//     named-scalar emission ring (x4 unroll), ONE __syncthreads per step
//     (barrier outside the t<mylen guard; loop bound lmax is block-uniform).
//   Backward (warps 0 and 2): equality-match backtrace:
//     tag' = first p with (m[t-1][p]+feat[t-1][p]) + w[tag][p] == m[t][tag]
// ============================================================================
__global__ __launch_bounds__(128, 4) void crf_fused(
    const float* __restrict__ feats,
    const float* __restrict__ weights,
    const int* __restrict__ lens,
    float* __restrict__ score_out,
    float* __restrict__ path_out,
    int T, int B)
{
    const int tid   = threadIdx.x;
    const int pair  = tid >> 6;         // 0 or 1
    const int j     = tid & 63;         // tag within pair
    const int lane  = tid & 31;
    const int wwarp = (tid >> 5) & 1;   // warp within pair

    __shared__ __align__(16) float w_sh[KTAG * KTAG];            // 16 KB
    __shared__ __align__(16) float fv_sh[2][2][KTAG];            // 1 KB
    __shared__ __align__(16) float mbuf[2][2][(CH + 1) * KTAG];  // 9.2 KB
    __shared__ __align__(16) float fbuf[2][2][CH * KTAG];        // 8 KB
    __shared__ float path_sh[2][MAXT];                           // 4 KB
    __shared__ float red_v[2][2];
    __shared__ int   red_i[2][2];
    __shared__ int   s_last[2];
    __shared__ int   s_len[2];
    __shared__ int   s_n;

    // Stage weights into shared once (terminal + backward).
    for (int q = tid; q < (KTAG * KTAG) / 4; q += 128)
        reinterpret_cast<float4*>(w_sh)[q] = reinterpret_cast<const float4*>(weights)[q];

    // Weight row w[j][0..63] as 32 float2 pairs in registers.
    float2 wp[KTAG / 2];
    {
        const float4* wrow = reinterpret_cast<const float4*>(weights + j * KTAG);
        #pragma unroll
        for (int i = 0; i < KTAG / 4; ++i) {
            float4 v = wrow[i];
            wp[2 * i]     = make_float2(v.x, v.y);
            wp[2 * i + 1] = make_float2(v.z, v.w);
        }
    }
    __syncthreads();

    while (true) {
        if (tid == 0) s_n = atomicAdd(&g_next, 2);     // grab TWO adjacent
        __syncthreads();
        const int n = s_n;
        if (n >= B) break;

        const int  nb    = n + pair;
        const bool valid = nb < B;
        const int  b     = valid ? g_order[nb] : g_order[n];   // safe fallback
        const int  mylen = valid ? lens[b] : 0;

        if (j == 0) s_len[pair] = mylen;
        const size_t base = (size_t)b * T * KTAG;
        const float* __restrict__ fcol = feats + base + j;
        float* __restrict__ m_out = g_m + base + j;

        fv_sh[pair][0][j] = (j == 0) ? 0.0f : NEGV;
        float curv = (j == 0) ? 0.0f : NEGV;

        // Emission prefetch: four named scalars (registers).
        float f0 = 0.0f, f1 = 0.0f, f2 = 0.0f, f3 = 0.0f;
        if (valid) {
            f0 = fcol[0];
            if (1 < mylen) f1 = fcol[1 * KTAG];
            if (2 < mylen) f2 = fcol[2 * KTAG];
            if (3 < mylen) f3 = fcol[3 * KTAG];
        }
        __syncthreads();
        const int lmax = max(s_len[0], s_len[1]);      // block-uniform

        // ---------------- forward (x4 unrolled; barrier UNGUARDED) ----------
        #define FWD_STEP(T_IDX, FREG)                                             \
            {                                                                     \
                if ((T_IDX) < mylen) {                                            \
                    const int rb = (T_IDX) & 1;                                   \
                    float a0 = -3.0e38f, a1 = -3.0e38f, a2 = -3.0e38f, a3 = -3.0e38f; \
                    float a4 = -3.0e38f, a5 = -3.0e38f, a6 = -3.0e38f, a7 = -3.0e38f; \
                    const float4* fvv = reinterpret_cast<const float4*>(fv_sh[pair][rb]); \
                    _Pragma("unroll")                                             \
                    for (int i = 0; i < 16; i += 2) {                             \
                        float4 p0 = fvv[i];                                       \
                        float4 p1 = fvv[i + 1];                                   \
                        float2 s0 = fadd2(make_float2(p0.x, p0.y), wp[2 * i + 0]); \
                        float2 s1 = fadd2(make_float2(p0.z, p0.w), wp[2 * i + 1]); \
                        float2 s2 = fadd2(make_float2(p1.x, p1.y), wp[2 * i + 2]); \
                        float2 s3 = fadd2(make_float2(p1.z, p1.w), wp[2 * i + 3]); \
                        a0 = fmaxf(a0, s0.x); a1 = fmaxf(a1, s0.y);               \
                        a2 = fmaxf(a2, s1.x); a3 = fmaxf(a3, s1.y);               \
                        a4 = fmaxf(a4, s2.x); a5 = fmaxf(a5, s2.y);               \
                        a6 = fmaxf(a6, s3.x); a7 = fmaxf(a7, s3.y);               \
                    }                                                             \
                    a0 = fmaxf(a0, a1); a2 = fmaxf(a2, a3);                       \
                    a4 = fmaxf(a4, a5); a6 = fmaxf(a6, a7);                       \
                    a0 = fmaxf(a0, a2); a4 = fmaxf(a4, a6);                       \
                    const float m = fmaxf(a0, a4);                                \
                    const float nf = m + (FREG);                                  \
                    curv = nf;                                                    \
                    fv_sh[pair][rb ^ 1][j] = nf;                                  \
                    m_out[(size_t)(T_IDX) * KTAG] = m;                            \
                    if ((T_IDX) + 4 < mylen)                                      \
                        (FREG) = fcol[(size_t)((T_IDX) + 4) * KTAG];              \
                }                                                                 \
                __syncthreads();                                                  \
            }

        for (int t0 = 0; t0 < lmax; t0 += 4) {
            FWD_STEP(t0 + 0, f0)
            FWD_STEP(t0 + 1, f1)
            FWD_STEP(t0 + 2, f2)
            FWD_STEP(t0 + 3, f3)
        }
        #undef FWD_STEP

        // Terminal: fv + weights[END=1][prev]; argmax, first-index tie-break.
        {
            float v = curv + w_sh[KTAG + j];
            int idx = j;
            #pragma unroll
            for (int off = 16; off; off >>= 1) {
                float ov = __shfl_xor_sync(0xffffffffu, v, off);
                int   oi = __shfl_xor_sync(0xffffffffu, idx, off);
                if (ov > v || (ov == v && oi < idx)) { v = ov; idx = oi; }
            }
            if (lane == 0) { red_v[pair][wwarp] = v; red_i[pair][wwarp] = idx; }
        }
        __syncthreads();
        if (j == 0 && valid) {
            float v0 = red_v[pair][0], v1 = red_v[pair][1];
            if (v1 > v0) { score_out[b] = v1; s_last[pair] = red_i[pair][1]; }
            else         { score_out[b] = v0; s_last[pair] = red_i[pair][0]; }
        }
        __syncthreads();

        // ---------------- backward (warps 0 and 2; one per pair) ------------
        if (wwarp == 0 && valid) {
            const int len = mylen;
            int tag = s_last[pair];
            const float* __restrict__ mrow = g_m + base;
            float* pathw = path_sh[pair];

            for (int q = len + lane; q < T; q += 32)
                pathw[q] = (float)tag;

            auto stage = [&](int lo, int bi) {
                const int r0 = lo - 1;
                #pragma unroll
                for (int q = lane; q < (CH + 1) * 16; q += 32) {
                    const int r = r0 + (q >> 4);
                    if (r >= 0 && r < len)
                        cp_async16(&mbuf[pair][bi][q * 4],
                                   mrow + (size_t)r * KTAG + (q & 15) * 4);
                }
                #pragma unroll
                for (int q = lane; q < CH * 16; q += 32) {
                    const int r = r0 + (q >> 4);
                    if (r >= 0 && r < len)
                        cp_async16(&fbuf[pair][bi][q * 4],
                                   feats + base + (size_t)r * KTAG + (q & 15) * 4);
                }
                CP_COMMIT();
            };

            const int hi0 = ((len + CH - 1) / CH) * CH;
            int bi = 0;
            stage(hi0 - CH, 0);

            for (int hi = hi0; hi > 0; hi -= CH) {
                const int lo = hi - CH;
                if (lo > 0) { stage(lo - CH, bi ^ 1); CP_WAIT(1); }
                else        { CP_WAIT(0); }
                __syncwarp();

                const float* mb = mbuf[pair][bi];
                const float* fb = fbuf[pair][bi];
                for (int t = hi - 1; t >= lo; --t) {
                    if (lane == 0 && t < len) pathw[t] = (float)tag;
                    if (t >= 1 && t < len) {
                        const float target = mb[(t - lo + 1) * KTAG + tag];
                        const float* mprev = mb + (t - lo) * KTAG;
                        const float* fprev = fb + (t - lo) * KTAG;
                        const float* wr = w_sh + tag * KTAG;
                        const float c0 = (mprev[lane]      + fprev[lane])      + wr[lane];
                        const float c1 = (mprev[lane + 32] + fprev[lane + 32]) + wr[lane + 32];
                        const unsigned e0 = __ballot_sync(0xffffffffu, c0 == target);
                        const unsigned e1 = __ballot_sync(0xffffffffu, c1 == target);
                        tag = e0 ? (__ffs(e0) - 1) : (__ffs(e1) + 31);
                    }
                }
                bi ^= 1;
                __syncwarp();
            }

            for (int q = lane; q < T; q += 32)
                path_out[(size_t)b * T + q] = pathw[q];
        }
        __syncthreads();   // smem reuse barrier before next grab
    }
}

extern "C" void kernel_launch(void* const* d_in, const int* in_sizes, int n_in,
                              void* d_out, int out_size) {
    const float* feats   = (const float*)d_in[0];
    const float* weights = (const float*)d_in[1];
    const int*   lens    = (const int*)d_in[2];

    const int B = in_sizes[2];
    const int K = KTAG;
    const int T = in_sizes[0] / (B * K);

    float* out = (float*)d_out;
    float* score_ptr;
    float* path_ptr;

    if (out_size == B * (T + 1)) {          // [score B | paths B*T]
        score_ptr = out;
        path_ptr  = out + B;
    } else if (out_size == B) {             // score only
        score_ptr = out;
        void* p; cudaGetSymbolAddress(&p, g_scratch);
        path_ptr = (float*)p;
    } else {                                // paths only
        path_ptr = out;
        void* p; cudaGetSymbolAddress(&p, g_scratch_score);
        score_ptr = (float*)p;
    }

    crf_order<<<1, 1024>>>(lens, B, T);
    crf_fused<<<GRID_PERSIST, 128>>>(feats, weights, lens, score_ptr, path_ptr, T, B);
}

// round 15
// speedup vs baseline: 1.7559x; 1.7559x over previous
#include <cuda_runtime.h>
#include <cuda_bf16.h>
#include <cstdint>

// Problem constants (fixed by the dataset): B=1024, T=512, K=64 tags.
#define KTAG 64
#define MAXB 1024
#define MAXT 512
#define NEGV -10000.0f

// Scratch: g_m[b][t][j] = max_prev(fv_prev + w[j][prev]) BEFORE emission.
__device__ float g_m[(size_t)MAXB * MAXT * KTAG];
__device__ float g_scratch[(size_t)MAXB * MAXT];
__device__ float g_scratch_score[MAXB];
__device__ int   g_order[MAXB];     // batch ids, descending len (LPT)
__device__ int   g_next;            // work-stealing counter

// ---- packed f32x2 add; movs are register-pairing only (elided by ptxas) ----
__device__ __forceinline__ float2 fadd2(float2 a, float2 b) {
    float2 r;
    asm("{\n\t"
        ".reg .b64 ra, rb, rc;\n\t"
        "mov.b64 ra, {%2, %3};\n\t"
        "mov.b64 rb, {%4, %5};\n\t"
        "add.rn.f32x2 rc, ra, rb;\n\t"
        "mov.b64 {%0, %1}, rc;\n\t"
        "}"
        : "=f"(r.x), "=f"(r.y)
        : "f"(a.x), "f"(a.y), "f"(b.x), "f"(b.y));
    return r;
}

// ---- cp.async helpers ----
__device__ __forceinline__ void cp_async16(void* smem_dst, const void* gmem_src) {
    unsigned int d = (unsigned int)__cvta_generic_to_shared(smem_dst);
    asm volatile("cp.async.cg.shared.global [%0], [%1], 16;" :: "r"(d), "l"(gmem_src));
}
#define CP_COMMIT()  asm volatile("cp.async.commit_group;")
#define CP_WAIT(n)   asm volatile("cp.async.wait_group %0;" :: "n"(n))

#define CH 8             // backward: timesteps per staged chunk
#define GRID_PERSIST 740 // 5 blocks/SM on 148 SMs

// ============================================================================
// Prologue: counting-sort batches by DESCENDING len into g_order (LPT order).
// ============================================================================
__global__ void crf_order(const int* __restrict__ lens, int B, int T)
{
    __shared__ int hist[MAXT + 1];
    __shared__ int off[MAXT + 1];
    const int tid = threadIdx.x;
    const int nt = blockDim.x;

    for (int l = tid; l <= T; l += nt) hist[l] = 0;
    __syncthreads();
    for (int b = tid; b < B; b += nt) atomicAdd(&hist[lens[b]], 1);
    __syncthreads();
    if (tid == 0) {
        int acc = 0;
        for (int l = T; l >= 0; --l) { off[l] = acc; acc += hist[l]; }
        g_next = 0;
    }
    __syncthreads();
    for (int b = tid; b < B; b += nt) {
        int pos = atomicAdd(&off[lens[b]], 1);
        g_order[pos] = b;
    }
}

// ============================================================================
// Persistent fused Viterbi: 64 threads (2 warps) per block; each block grabs
// batches LPT-first until exhausted. Per batch:
//   Forward (both warps): thread j owns next-tag j;
//     new_fv[j] = max_prev(fv[prev] + w[j][prev]) + feat[t][j]
//     Step is TWO-PHASE: (1) all 16 LDS.128 of fv into registers back-to-back
//     (MLP ~16 on the shared loads), (2) FADD2+FMNMX math. This stops ptxas
//     from serializing LDS->math per float4 (the ~780-cyc step observed).
//   Backward (warp 0): equality-match backtrace:
//     tag' = first p with (m[t-1][p]+feat[t-1][p]) + w[tag][p] == m[t][tag]
// ============================================================================
__global__ __launch_bounds__(KTAG) void crf_fused(
    const float* __restrict__ feats,
    const float* __restrict__ weights,
    const int* __restrict__ lens,
    float* __restrict__ score_out,
    float* __restrict__ path_out,
    int T, int B)
{
    const int j = threadIdx.x;          // next tag (forward phase)
    const int lane = j & 31;
    const int warp = j >> 5;

    __shared__ __align__(16) float fv_sh[2][KTAG];
    __shared__ __align__(16) float w_sh[KTAG * KTAG];            // 16 KB
    __shared__ __align__(16) float mbuf[2][(CH + 1) * KTAG];     // 4.6 KB
    __shared__ __align__(16) float fbuf[2][CH * KTAG];           // 4 KB
    __shared__ float path_sh[MAXT];                              // 2 KB
    __shared__ float red_v[2];
    __shared__ int   red_i[2];
    __shared__ int   s_last;
    __shared__ int   s_n;

    // Stage weights into shared (terminal + backward); once per block.
    for (int q = j; q < (KTAG * KTAG) / 4; q += KTAG)
        reinterpret_cast<float4*>(w_sh)[q] = reinterpret_cast<const float4*>(weights)[q];

    // Weight row w[j][0..63] as 32 float2 pairs in registers; once per block.
    float2 wp[KTAG / 2];
    {
        const float4* wrow = reinterpret_cast<const float4*>(weights + j * KTAG);
        #pragma unroll
        for (int i = 0; i < KTAG / 4; ++i) {
            float4 v = wrow[i];
            wp[2 * i]     = make_float2(v.x, v.y);
            wp[2 * i + 1] = make_float2(v.z, v.w);
        }
    }

    while (true) {
        if (j == 0) s_n = atomicAdd(&g_next, 1);
        __syncthreads();
        const int n = s_n;
        if (n >= B) break;
        const int b = g_order[n];

        const int len = lens[b];            // 1..T
        const size_t base = (size_t)b * T * KTAG;
        const float* __restrict__ fcol = feats + base + j;
        float* __restrict__ m_out = g_m + base + j;

        fv_sh[0][j] = (j == 0) ? 0.0f : NEGV;
        float curv = (j == 0) ? 0.0f : NEGV;

        // Emission prefetch: four named scalars (registers).
        float f0 = fcol[0];
        float f1 = (1 < len) ? fcol[1 * KTAG] : 0.0f;
        float f2 = (2 < len) ? fcol[2 * KTAG] : 0.0f;
        float f3 = (3 < len) ? fcol[3 * KTAG] : 0.0f;

        __syncthreads();

        // ---------------- forward (unrolled x4, uniform guards) ------------
        #define FWD_STEP(T_IDX, FREG)                                             \
            if ((T_IDX) < len) {                                                  \
                const int rb = (T_IDX) & 1;                                       \
                const float4* fvv = reinterpret_cast<const float4*>(fv_sh[rb]);   \
                /* phase 1: batch ALL shared loads (16x LDS.128, high MLP) */     \
                float4 rr[16];                                                    \
                _Pragma("unroll")                                                 \
                for (int i = 0; i < 16; ++i) rr[i] = fvv[i];                      \
                /* phase 2: math (32 FADD2 + 64 FMNMX, 8 chains) */               \
                float a0 = -3.0e38f, a1 = -3.0e38f, a2 = -3.0e38f, a3 = -3.0e38f; \
                float a4 = -3.0e38f, a5 = -3.0e38f, a6 = -3.0e38f, a7 = -3.0e38f; \
                _Pragma("unroll")                                                 \
                for (int i = 0; i < 16; i += 2) {                                 \
                    float2 s0 = fadd2(make_float2(rr[i].x, rr[i].y), wp[2 * i + 0]); \
                    float2 s1 = fadd2(make_float2(rr[i].z, rr[i].w), wp[2 * i + 1]); \
                    float2 s2 = fadd2(make_float2(rr[i + 1].x, rr[i + 1].y), wp[2 * i + 2]); \
                    float2 s3 = fadd2(make_float2(rr[i + 1].z, rr[i + 1].w), wp[2 * i + 3]); \
                    a0 = fmaxf(a0, s0.x); a1 = fmaxf(a1, s0.y);                   \
                    a2 = fmaxf(a2, s1.x); a3 = fmaxf(a3, s1.y);                   \
                    a4 = fmaxf(a4, s2.x); a5 = fmaxf(a5, s2.y);                   \
                    a6 = fmaxf(a6, s3.x); a7 = fmaxf(a7, s3.y);                   \
                }                                                                 \
                a0 = fmaxf(a0, a1); a2 = fmaxf(a2, a3);                           \
                a4 = fmaxf(a4, a5); a6 = fmaxf(a6, a7);                           \
                a0 = fmaxf(a0, a2); a4 = fmaxf(a4, a6);                           \
                const float m = fmaxf(a0, a4);                                    \
                const float nf = m + (FREG);                                      \
                curv = nf;                                                        \
                fv_sh[rb ^ 1][j] = nf;                                            \
                m_out[(size_t)(T_IDX) * KTAG] = m;                                \
                if ((T_IDX) + 4 < len)                                            \
                    (FREG) = fcol[(size_t)((T_IDX) + 4) * KTAG];                  \
                __syncthreads();                                                  \
            }

        for (int t0 = 0; t0 < len; t0 += 4) {
            FWD_STEP(t0 + 0, f0)
            FWD_STEP(t0 + 1, f1)
            FWD_STEP(t0 + 2, f2)
            FWD_STEP(t0 + 3, f3)
        }
        #undef FWD_STEP

        // Terminal: fv + weights[END=1][prev]; argmax, first-index tie-break.
        {
            float v = curv + w_sh[KTAG + j];
            int idx = j;
            #pragma unroll
            for (int off = 16; off; off >>= 1) {
                float ov = __shfl_xor_sync(0xffffffffu, v, off);
                int   oi = __shfl_xor_sync(0xffffffffu, idx, off);
                if (ov > v || (ov == v && oi < idx)) { v = ov; idx = oi; }
            }
            if (lane == 0) { red_v[warp] = v; red_i[warp] = idx; }
        }
        __syncthreads();
        if (j == 0) {
            float v0 = red_v[0], v1 = red_v[1];
            if (v1 > v0) { score_out[b] = v1; s_last = red_i[1]; }
            else         { score_out[b] = v0; s_last = red_i[0]; }
        }
        __syncthreads();

        // ---------------- backward (warp 0 only) ----------------
        if (warp == 0) {
            int tag = s_last;
            const float* __restrict__ mrow = g_m + base;

            for (int q = len + lane; q < T; q += 32)
                path_sh[q] = (float)tag;

            auto stage = [&](int lo, int bi) {
                const int r0 = lo - 1;
                #pragma unroll
                for (int q = lane; q < (CH + 1) * 16; q += 32) {
                    const int r = r0 + (q >> 4);
                    if (r >= 0 && r < len)
                        cp_async16(&mbuf[bi][q * 4], mrow + (size_t)r * KTAG + (q & 15) * 4);
                }
                #pragma unroll
                for (int q = lane; q < CH * 16; q += 32) {
                    const int r = r0 + (q >> 4);
                    if (r >= 0 && r < len)
                        cp_async16(&fbuf[bi][q * 4], feats + base + (size_t)r * KTAG + (q & 15) * 4);
                }
                CP_COMMIT();
            };

            const int hi0 = ((len + CH - 1) / CH) * CH;
            int bi = 0;
            stage(hi0 - CH, 0);

            for (int hi = hi0; hi > 0; hi -= CH) {
                const int lo = hi - CH;
                if (lo > 0) { stage(lo - CH, bi ^ 1); CP_WAIT(1); }
                else        { CP_WAIT(0); }
                __syncwarp();

                const float* mb = mbuf[bi];
                const float* fb = fbuf[bi];
                for (int t = hi - 1; t >= lo; --t) {
                    if (lane == 0 && t < len) path_sh[t] = (float)tag;
                    if (t >= 1 && t < len) {
                        const float target = mb[(t - lo + 1) * KTAG + tag];
                        const float* mprev = mb + (t - lo) * KTAG;
                        const float* fprev = fb + (t - lo) * KTAG;
                        const float* wr = w_sh + tag * KTAG;
                        const float c0 = (mprev[lane]      + fprev[lane])      + wr[lane];
                        const float c1 = (mprev[lane + 32] + fprev[lane + 32]) + wr[lane + 32];
                        const unsigned e0 = __ballot_sync(0xffffffffu, c0 == target);
                        const unsigned e1 = __ballot_sync(0xffffffffu, c1 == target);
                        tag = e0 ? (__ffs(e0) - 1) : (__ffs(e1) + 31);
                    }
                }
                bi ^= 1;
                __syncwarp();
            }

            for (int q = lane; q < T; q += 32)
                path_out[(size_t)b * T + q] = path_sh[q];
        }
        __syncthreads();   // smem reuse barrier before next grab
    }
}

extern "C" void kernel_launch(void* const* d_in, const int* in_sizes, int n_in,
                              void* d_out, int out_size) {
    const float* feats   = (const float*)d_in[0];
    const float* weights = (const float*)d_in[1];
    const int*   lens    = (const int*)d_in[2];

    const int B = in_sizes[2];
    const int K = KTAG;
    const int T = in_sizes[0] / (B * K);

    float* out = (float*)d_out;
    float* score_ptr;
    float* path_ptr;

    if (out_size == B * (T + 1)) {          // [score B | paths B*T]
        score_ptr = out;
        path_ptr  = out + B;
    } else if (out_size == B) {             // score only
        score_ptr = out;
        void* p; cudaGetSymbolAddress(&p, g_scratch);
        path_ptr = (float*)p;
    } else {                                // paths only
        path_ptr = out;
        void* p; cudaGetSymbolAddress(&p, g_scratch_score);
        score_ptr = (float*)p;
    }

    crf_order<<<1, 1024>>>(lens, B, T);
    const int grid = (B < GRID_PERSIST) ? B : GRID_PERSIST;
    crf_fused<<<grid, KTAG>>>(feats, weights, lens, score_ptr, path_ptr, T, B);
}